// round 15
// baseline (speedup 1.0000x reference)
#include <cuda_runtime.h>

#define B 64
#define H 768
#define E 128

#define KS 12                 // GEMM k-splits (K chunk = 64 floats)
#define NGEMM 192             // one block per GEMM tile; whole grid
#define NROW 128              // blocks 0..127 also reduce core row e=bid
#define NCOMB 64              // blocks 128..191 combine (1 b-row each)

__device__ float g_S2[E];              // full S2[e] (one row-block per e)
__device__ float g_P[3][KS][B][E];     // [mat][ks][b][e] gemm partials
__device__ unsigned g_arrive;          // all-blocks arrive; self-resetting
__device__ unsigned g_done2;           // combiner-done; self-resetting

__global__ void __launch_bounds__(256)
k_all(const float* __restrict__ core,
      const float* __restrict__ hs, const float* __restrict__ rs,
      const float* __restrict__ ts, const float* __restrict__ we,
      const float* __restrict__ wr, const float* __restrict__ be,
      const float* __restrict__ br, float* __restrict__ out) {
    __shared__ float4 s_src[3][32][18];  // gemm src tiles (swizzled)
    __shared__ float4 s_w[2][16][18];    // gemm We/Wr tiles / scratch

    const int bid = blockIdx.x;
    const int tid = threadIdx.x;
    const bool has_row = (bid < NROW);

    // ---- core row batch 1: 8 independent float4 loads, issued BEFORE the
    //      GEMM so their DRAM latency hides under the mainloop.
    const float4* src = reinterpret_cast<const float4*>(core) + (size_t)bid * 4096;
    float4 v0, v1, v2, v3, v4, v5, v6, v7;
    if (has_row) {
        v0 = __ldg(src + tid);        v1 = __ldg(src + tid + 256);
        v2 = __ldg(src + tid + 512);  v3 = __ldg(src + tid + 768);
        v4 = __ldg(src + tid + 1024); v5 = __ldg(src + tid + 1280);
        v6 = __ldg(src + tid + 1536); v7 = __ldg(src + tid + 1792);
    }

    // ---- triple GEMM (R2-proven): 32b x 16e x 64k tile, every block --------
    const int ks = bid % KS, ec = (bid / KS) & 7, bg = bid / (KS * 8);
    const int b0 = bg * 32, e0 = ec * 16;
    const int c0 = ks * 16;

    const float4* g0 = reinterpret_cast<const float4*>(hs);
    const float4* g1 = reinterpret_cast<const float4*>(rs);
    const float4* g2 = reinterpret_cast<const float4*>(ts);
#pragma unroll
    for (int i = tid; i < 512; i += 256) {
        const int row = i >> 4, c4 = i & 15;
        const size_t gidx = (size_t)(b0 + row) * 192 + c0 + c4;
        const int sc = c4 ^ (row & 7);
        s_src[0][row][sc] = g0[gidx];
        s_src[1][row][sc] = g1[gidx];
        s_src[2][row][sc] = g2[gidx];
    }
    {
        const int row = tid >> 4, c4 = tid & 15;
        const size_t gidx = (size_t)(e0 + row) * 192 + c0 + c4;
        const int sc = c4 ^ (row & 7);
        s_w[0][row][sc] = reinterpret_cast<const float4*>(we)[gidx];
        s_w[1][row][sc] = reinterpret_cast<const float4*>(wr)[gidx];
    }
    __syncthreads();

    const int te = tid & 15;
    const int tb = tid >> 4;
    const int ba = 2 * tb, bb = ba + 1;

    float h0 = 0.f, h1 = 0.f, r0 = 0.f, r1 = 0.f, t0 = 0.f, t1 = 0.f;
#pragma unroll
    for (int k4 = 0; k4 < 16; k4++) {
        const float4 vwe = s_w[0][te][k4 ^ (te & 7)];
        const float4 vwr = s_w[1][te][k4 ^ (te & 7)];
        const int sa = k4 ^ (ba & 7), sb = k4 ^ (bb & 7);
        float4 a, c;
        a = s_src[0][ba][sa]; c = s_src[0][bb][sb];
        h0 += vwe.x * a.x + vwe.y * a.y + vwe.z * a.z + vwe.w * a.w;
        h1 += vwe.x * c.x + vwe.y * c.y + vwe.z * c.z + vwe.w * c.w;
        a = s_src[1][ba][sa]; c = s_src[1][bb][sb];
        r0 += vwr.x * a.x + vwr.y * a.y + vwr.z * a.z + vwr.w * a.w;
        r1 += vwr.x * c.x + vwr.y * c.y + vwr.z * c.z + vwr.w * c.w;
        a = s_src[2][ba][sa]; c = s_src[2][bb][sb];
        t0 += vwe.x * a.x + vwe.y * a.y + vwe.z * a.z + vwe.w * a.w;
        t1 += vwe.x * c.x + vwe.y * c.y + vwe.z * c.z + vwe.w * c.w;
    }

    // ---- core row batch 2 issued before epilogue stores (overlaps them) ----
    float4 w0, w1, w2, w3, w4, w5, w6, w7;
    if (has_row) {
        w0 = __ldg(src + tid + 2048); w1 = __ldg(src + tid + 2304);
        w2 = __ldg(src + tid + 2560); w3 = __ldg(src + tid + 2816);
        w4 = __ldg(src + tid + 3072); w5 = __ldg(src + tid + 3328);
        w6 = __ldg(src + tid + 3584); w7 = __ldg(src + tid + 3840);
    }

    {   // GEMM epilogue
        const int bga = b0 + ba, bgb = b0 + bb;
        const int e = e0 + te;
        g_P[0][ks][bga][e] = h0;  g_P[0][ks][bgb][e] = h1;
        g_P[1][ks][bga][e] = r0;  g_P[1][ks][bgb][e] = r1;
        g_P[2][ks][bga][e] = t0;  g_P[2][ks][bgb][e] = t1;
    }

    if (has_row) {
        float s = ((((v0.x + v0.y) + (v0.z + v0.w)) + ((v1.x + v1.y) + (v1.z + v1.w)))
                +  (((v2.x + v2.y) + (v2.z + v2.w)) + ((v3.x + v3.y) + (v3.z + v3.w))))
                + ((((v4.x + v4.y) + (v4.z + v4.w)) + ((v5.x + v5.y) + (v5.z + v5.w)))
                +  (((v6.x + v6.y) + (v6.z + v6.w)) + ((v7.x + v7.y) + (v7.z + v7.w))));
        s +=    ((((w0.x + w0.y) + (w0.z + w0.w)) + ((w1.x + w1.y) + (w1.z + w1.w)))
                +  (((w2.x + w2.y) + (w2.z + w2.w)) + ((w3.x + w3.y) + (w3.z + w3.w))))
                + ((((w4.x + w4.y) + (w4.z + w4.w)) + ((w5.x + w5.y) + (w5.z + w5.w)))
                +  (((w6.x + w6.y) + (w6.z + w6.w)) + ((w7.x + w7.y) + (w7.z + w7.w))));
#pragma unroll
        for (int o = 16; o > 0; o >>= 1) s += __shfl_xor_sync(0xffffffffu, s, o);
        __syncthreads();                 // mainloop smem reads done -> reuse s_w
        float* ws = reinterpret_cast<float*>(s_w);
        if ((tid & 31) == 0) ws[tid >> 5] = s;
        __syncthreads();
        if (tid == 0) {
            float tot = 0.f;
#pragma unroll
            for (int wI = 0; wI < 8; wI++) tot += ws[wI];
            g_S2[bid] = tot;             // full S2 for e = bid
        }
    }

    // ---- arrive (every block, after ALL its work) -------------------------
    __threadfence();
    __syncthreads();
    if (tid == 0) atomicAdd(&g_arrive, 1u);

    if (has_row) return;                 // row+GEMM blocks exit

    // ---- combine (blocks 128..191): b = bid - 128 -------------------------
    if (tid == 0) {
        volatile unsigned* p = &g_arrive;
        while (*p < NGEMM) __nanosleep(16);
    }
    __syncthreads();
    __threadfence();

    const int b = bid - NROW;
    float4* sm    = reinterpret_cast<float4*>(s_w);   // [3][2][32] = 192 f4
    float4* sbias = sm + 192;                         // be4, br4 (2*32)
    float4* ss2q  = sm + 256;                         // S2 quads (32)

    if (tid < 192) {
        const int m = tid >> 6, rem = tid & 63;
        const int kh = rem >> 5, e4 = rem & 31;
        // 6 independent coalesced f4 loads (ks stride = B*E/4 = 2048 f4)
        const float4* base =
            reinterpret_cast<const float4*>(&g_P[m][kh * 6][b][0]) + e4;
        const float4 a0 = __ldg(base);
        const float4 a1 = __ldg(base + 2048);
        const float4 a2 = __ldg(base + 4096);
        const float4 a3 = __ldg(base + 6144);
        const float4 a4 = __ldg(base + 8192);
        const float4 a5 = __ldg(base + 10240);
        float4 f;
        f.x = (a0.x + a1.x) + (a2.x + a3.x) + (a4.x + a5.x);
        f.y = (a0.y + a1.y) + (a2.y + a3.y) + (a4.y + a5.y);
        f.z = (a0.z + a1.z) + (a2.z + a3.z) + (a4.z + a5.z);
        f.w = (a0.w + a1.w) + (a2.w + a3.w) + (a4.w + a5.w);
        sm[(m * 2 + kh) * 32 + e4] = f;
    } else if (tid < 224) {
        const int l = tid - 192;
        sbias[l]      = __ldg(reinterpret_cast<const float4*>(be) + l);
        sbias[32 + l] = __ldg(reinterpret_cast<const float4*>(br) + l);
        ss2q[l]       = __ldg(reinterpret_cast<const float4*>(g_S2) + l);
    }
    __syncthreads();

    if (tid < 96) {                       // fold the two ks-halves
        const int m = tid >> 5, e4 = tid & 31;
        const float4 qa = sm[(m * 2) * 32 + e4];
        const float4 qb = sm[(m * 2 + 1) * 32 + e4];
        sm[(m * 2) * 32 + e4] =
            make_float4(qa.x + qb.x, qa.y + qb.y, qa.z + qb.z, qa.w + qb.w);
    }
    __syncthreads();

    if (tid < 32) {                       // triple product + warp reduce
        const float4 h4 = sm[tid];
        const float4 r4 = sm[64 + tid];
        const float4 t4 = sm[128 + tid];
        const float4 vb = sbias[tid];
        const float4 vr = sbias[32 + tid];
        const float4 s2 = ss2q[tid];
        float v = (h4.x + vb.x) * (r4.x + vr.x) * (t4.x + vb.x) * s2.x
                + (h4.y + vb.y) * (r4.y + vr.y) * (t4.y + vb.y) * s2.y
                + (h4.z + vb.z) * (r4.z + vr.z) * (t4.z + vb.z) * s2.z
                + (h4.w + vb.w) * (r4.w + vr.w) * (t4.w + vb.w) * s2.w;
#pragma unroll
        for (int o = 16; o > 0; o >>= 1) v += __shfl_xor_sync(0xffffffffu, v, o);
        if (tid == 0) out[b] = -v;
    }
    __syncthreads();

    if (tid == 0) {                       // counter reset for graph replay
        const unsigned d = atomicAdd(&g_done2, 1u);
        if (d == NCOMB - 1) {
            g_arrive = 0u;
            __threadfence();
            g_done2 = 0u;
        }
    }
}

// ---------------------------------------------------------------------------
extern "C" void kernel_launch(void* const* d_in, const int* in_sizes, int n_in,
                              void* d_out, int out_size) {
    const float* head = (const float*)d_in[0];
    const float* rel  = (const float*)d_in[1];
    const float* tail = (const float*)d_in[2];
    const float* We   = (const float*)d_in[3];
    const float* be   = (const float*)d_in[4];
    const float* Wr   = (const float*)d_in[5];
    const float* br   = (const float*)d_in[6];
    const float* core = (const float*)d_in[7];
    float* out = (float*)d_out;

    k_all<<<NGEMM, 256>>>(core, head, rel, tail, We, Wr, be, br, out);
}

// round 16
// speedup vs baseline: 1.1575x; 1.1575x over previous
#include <cuda_runtime.h>

#define B 64
#define H 768
#define E 128

#define NRED 256    // core-reduce blocks (32 KB each), bids [0,256)
#define KS 12       // GEMM k-splits
#define NGEMM 192   // 12 ks x 8 echunk x 2 bgroup, bids [256,448)
#define GRID (NRED + NGEMM)

// Folded accumulators. Zero at module load; each combine run re-zeroes them
// after reading, so every graph replay starts from zero.
__device__ float g_S2[E];              // S2[e], atomically folded (2 adders/e)
__device__ float g_P[3][B][E];         // h/r/t sums, atomically folded (12/e)
__device__ unsigned g_done2;           // combiner-done counter; self-resetting

// ---------------------------------------------------------------------------
// Kernel A: blocks [0,256) reduce core (MLP=8) -> atomicAdd into g_S2;
// blocks [256,448) triple GEMM 32b x 16e x 64k -> atomicAdd into g_P.
// ---------------------------------------------------------------------------
__global__ void k_fused(const float* __restrict__ core,
                        const float* __restrict__ hs, const float* __restrict__ rs,
                        const float* __restrict__ ts, const float* __restrict__ we,
                        const float* __restrict__ wr) {
    __shared__ float4 s_src[3][32][18];  // gemm src tiles (swizzled)
    __shared__ float4 s_w[2][16][18];    // gemm We/Wr tiles

    const int bid = blockIdx.x;
    const int tid = threadIdx.x;

    if (bid < NRED) {
        const float4* src = reinterpret_cast<const float4*>(core) + (size_t)bid * 2048;
        const float4 v0 = __ldg(src + tid);
        const float4 v1 = __ldg(src + tid + 256);
        const float4 v2 = __ldg(src + tid + 512);
        const float4 v3 = __ldg(src + tid + 768);
        const float4 v4 = __ldg(src + tid + 1024);
        const float4 v5 = __ldg(src + tid + 1280);
        const float4 v6 = __ldg(src + tid + 1536);
        const float4 v7 = __ldg(src + tid + 1792);
        float s = ((((v0.x + v0.y) + (v0.z + v0.w)) + ((v1.x + v1.y) + (v1.z + v1.w)))
                +  (((v2.x + v2.y) + (v2.z + v2.w)) + ((v3.x + v3.y) + (v3.z + v3.w))))
                + ((((v4.x + v4.y) + (v4.z + v4.w)) + ((v5.x + v5.y) + (v5.z + v5.w)))
                +  (((v6.x + v6.y) + (v6.z + v6.w)) + ((v7.x + v7.y) + (v7.z + v7.w))));
#pragma unroll
        for (int o = 16; o > 0; o >>= 1) s += __shfl_xor_sync(0xffffffffu, s, o);
        float* ws = reinterpret_cast<float*>(s_w);
        if ((tid & 31) == 0) ws[tid >> 5] = s;
        __syncthreads();
        if (tid == 0) {
            float tot = 0.f;
#pragma unroll
            for (int w = 0; w < 8; w++) tot += ws[w];
            atomicAdd(&g_S2[bid >> 1], tot);   // fold 2 partials per e
        }
        return;
    }

    const int lin = bid - NRED;
    const int ks = lin % KS, ec = (lin / KS) & 7, bg = lin / (KS * 8);
    const int b0 = bg * 32, e0 = ec * 16;
    const int c0 = ks * 16;

    const float4* g0 = reinterpret_cast<const float4*>(hs);
    const float4* g1 = reinterpret_cast<const float4*>(rs);
    const float4* g2 = reinterpret_cast<const float4*>(ts);
#pragma unroll
    for (int i = tid; i < 512; i += 256) {
        const int row = i >> 4, c4 = i & 15;
        const size_t gidx = (size_t)(b0 + row) * 192 + c0 + c4;
        const int sc = c4 ^ (row & 7);
        s_src[0][row][sc] = g0[gidx];
        s_src[1][row][sc] = g1[gidx];
        s_src[2][row][sc] = g2[gidx];
    }
    {
        const int row = tid >> 4, c4 = tid & 15;
        const size_t gidx = (size_t)(e0 + row) * 192 + c0 + c4;
        const int sc = c4 ^ (row & 7);
        s_w[0][row][sc] = reinterpret_cast<const float4*>(we)[gidx];
        s_w[1][row][sc] = reinterpret_cast<const float4*>(wr)[gidx];
    }
    __syncthreads();

    const int te = tid & 15;
    const int tb = tid >> 4;
    const int ba = 2 * tb, bb = ba + 1;

    float h0 = 0.f, h1 = 0.f, r0 = 0.f, r1 = 0.f, t0 = 0.f, t1 = 0.f;
#pragma unroll
    for (int k4 = 0; k4 < 16; k4++) {
        const float4 vwe = s_w[0][te][k4 ^ (te & 7)];
        const float4 vwr = s_w[1][te][k4 ^ (te & 7)];
        const int sa = k4 ^ (ba & 7), sb = k4 ^ (bb & 7);
        float4 a, c;
        a = s_src[0][ba][sa]; c = s_src[0][bb][sb];
        h0 += vwe.x * a.x + vwe.y * a.y + vwe.z * a.z + vwe.w * a.w;
        h1 += vwe.x * c.x + vwe.y * c.y + vwe.z * c.z + vwe.w * c.w;
        a = s_src[1][ba][sa]; c = s_src[1][bb][sb];
        r0 += vwr.x * a.x + vwr.y * a.y + vwr.z * a.z + vwr.w * a.w;
        r1 += vwr.x * c.x + vwr.y * c.y + vwr.z * c.z + vwr.w * c.w;
        a = s_src[2][ba][sa]; c = s_src[2][bb][sb];
        t0 += vwe.x * a.x + vwe.y * a.y + vwe.z * a.z + vwe.w * a.w;
        t1 += vwe.x * c.x + vwe.y * c.y + vwe.z * c.z + vwe.w * c.w;
    }

    // folding epilogue: 6 spread-address REDG.ADD per thread (cheap)
    const int bga = b0 + ba, bgb = b0 + bb;
    const int e = e0 + te;
    atomicAdd(&g_P[0][bga][e], h0);  atomicAdd(&g_P[0][bgb][e], h1);
    atomicAdd(&g_P[1][bga][e], r0);  atomicAdd(&g_P[1][bgb][e], r1);
    atomicAdd(&g_P[2][bga][e], t0);  atomicAdd(&g_P[2][bgb][e], t1);
}

// ---------------------------------------------------------------------------
// Kernel B: minimal combine. 64 blocks x 384 threads; ONE coalesced float
// load per thread (3 x 128 = 384), one smem exchange, one warp reduce.
// Re-zeroes g_P (per block) and g_S2 (last block) for the next replay.
// ---------------------------------------------------------------------------
__global__ void k_combine(const float* __restrict__ be, const float* __restrict__ br,
                          float* __restrict__ out) {
    __shared__ float sh[3][128];
    __shared__ float s2s[128];
    __shared__ float sb[2][128];
    __shared__ float sred[4];

    const int b = blockIdx.x;
    const int tid = threadIdx.x;           // 0..383
    const int m = tid >> 7;                // matrix 0/1/2
    const int e = tid & 127;

    // parallel load phase: g_P value + (s2 | be | br) per thread role
    const float val = g_P[m][b][e];
    if (m == 0)      s2s[e]   = g_S2[e];
    else if (m == 1) sb[0][e] = be[e];
    else             sb[1][e] = br[e];
    sh[m][e] = val;
    __syncthreads();

    // re-zero this block's g_P slice for the next replay
    g_P[m][b][e] = 0.f;

    if (tid < 128) {
        const float h = sh[0][tid] + sb[0][tid];
        const float r = sh[1][tid] + sb[1][tid];
        const float t = sh[2][tid] + sb[0][tid];
        float v = h * r * t * s2s[tid];
#pragma unroll
        for (int o = 16; o > 0; o >>= 1) v += __shfl_xor_sync(0xffffffffu, v, o);
        if ((tid & 31) == 0) sred[tid >> 5] = v;
    }
    __syncthreads();
    if (tid == 0) out[b] = -((sred[0] + sred[1]) + (sred[2] + sred[3]));

    // last combiner zeroes g_S2 (all blocks have read it) and resets counter
    if (tid == 0) {
        __threadfence();
        const unsigned d = atomicAdd(&g_done2, 1u);
        if (d == B - 1) {
            for (int i = 0; i < E; i++) g_S2[i] = 0.f;
            __threadfence();
            g_done2 = 0u;
        }
    }
}

// ---------------------------------------------------------------------------
extern "C" void kernel_launch(void* const* d_in, const int* in_sizes, int n_in,
                              void* d_out, int out_size) {
    const float* head = (const float*)d_in[0];
    const float* rel  = (const float*)d_in[1];
    const float* tail = (const float*)d_in[2];
    const float* We   = (const float*)d_in[3];
    const float* be   = (const float*)d_in[4];
    const float* Wr   = (const float*)d_in[5];
    const float* br   = (const float*)d_in[6];
    const float* core = (const float*)d_in[7];
    float* out = (float*)d_out;

    k_fused<<<GRID, 256>>>(core, head, rel, tail, We, Wr);
    k_combine<<<B, 384>>>(be, br, out);
}